// round 2
// baseline (speedup 1.0000x reference)
#include <cuda_runtime.h>
#include <math.h>

// GMM score: out[n] = prod_c ( (x_n - m_c)^T A_c (x_n - m_c) )^{w_c}
//          = exp( sum_c w_c * log d[n,c] )
// N = 262144, C = 16, D = 64 (compile-time constants; N taken from in_sizes).

#define D 64
#define C 16
#define NTHREADS 256

__global__ __launch_bounds__(NTHREADS, 2)
void gmm_score_kernel(const float* __restrict__ X,       // [N, D]
                      const float* __restrict__ Ainv,    // [C, D, D]
                      const float* __restrict__ Means,   // [C, D]
                      const float* __restrict__ W,       // [C]
                      float* __restrict__ out, int N)
{
    __shared__ float sA[D * D];     // 16 KB: current component's inverse covariance
    __shared__ float sDelta[D];     // m_c - m_{c-1}
    __shared__ float sPrev[D];      // previous mean
    __shared__ float sW;

    const int tid = threadIdx.x;
    const int n = blockIdx.x * NTHREADS + tid;
    const bool active = (n < N);

    // z starts as x_n; per component we subtract the mean delta so we never
    // need x and z live simultaneously (keeps register count ~96, no spills).
    float z[D];
    if (active) {
        const float4* xg = reinterpret_cast<const float4*>(X + (size_t)n * D);
        #pragma unroll
        for (int j = 0; j < D / 4; j++) {
            float4 v = xg[j];
            z[4*j+0] = v.x; z[4*j+1] = v.y; z[4*j+2] = v.z; z[4*j+3] = v.w;
        }
    } else {
        #pragma unroll
        for (int j = 0; j < D; j++) z[j] = 0.0f;
    }
    if (tid < D) sPrev[tid] = 0.0f;

    float logacc = 0.0f;

    for (int c = 0; c < C; c++) {
        __syncthreads();  // protect sA/sDelta from previous iteration's readers

        // Stage A_c into smem (vectorized, cooperative)
        const float4* Ag  = reinterpret_cast<const float4*>(Ainv + (size_t)c * D * D);
        float4*       As4 = reinterpret_cast<float4*>(sA);
        #pragma unroll
        for (int t = tid; t < (D * D) / 4; t += NTHREADS)
            As4[t] = Ag[t];

        if (tid < D) {
            float mnew = Means[c * D + tid];
            sDelta[tid] = mnew - sPrev[tid];
            sPrev[tid]  = mnew;
        }
        if (tid == 0) sW = W[c];
        __syncthreads();

        // z = x - m_c  (incremental update)
        #pragma unroll
        for (int j = 0; j < D; j++) z[j] -= sDelta[j];

        // Quadratic form: acc = sum_i z_i * (A_c[i,:] . z)
        // 4 independent FMA chains per row for ILP; LDS.128 broadcast reads.
        float acc = 0.0f;
        #pragma unroll 4
        for (int i = 0; i < D; i++) {
            const float4* row = reinterpret_cast<const float4*>(sA + i * D);
            float s0 = 0.f, s1 = 0.f, s2 = 0.f, s3 = 0.f;
            #pragma unroll
            for (int j4 = 0; j4 < D / 4; j4++) {
                float4 a = row[j4];
                s0 = fmaf(a.x, z[4*j4+0], s0);
                s1 = fmaf(a.y, z[4*j4+1], s1);
                s2 = fmaf(a.z, z[4*j4+2], s2);
                s3 = fmaf(a.w, z[4*j4+3], s3);
            }
            acc = fmaf(z[i], (s0 + s1) + (s2 + s3), acc);
        }

        // d > 0 guaranteed (SPD + 0.1 I); accumulate in log domain.
        // acc can be garbage for inactive threads; guard the log.
        logacc = fmaf(sW, logf(active ? acc : 1.0f), logacc);
    }

    if (active) out[n] = expf(logacc);
}

extern "C" void kernel_launch(void* const* d_in, const int* in_sizes, int n_in,
                              void* d_out, int out_size)
{
    const float* X     = (const float*)d_in[0];   // inputs          [N, 64]
    const float* Ainv  = (const float*)d_in[1];   // covariances_inv [16, 64, 64]
    const float* Means = (const float*)d_in[2];   // means           [16, 64]
    const float* W     = (const float*)d_in[3];   // weights         [16]
    float* out = (float*)d_out;

    const int N = in_sizes[0] / D;
    const int grid = (N + NTHREADS - 1) / NTHREADS;
    gmm_score_kernel<<<grid, NTHREADS>>>(X, Ainv, Means, W, out, N);
}

// round 4
// speedup vs baseline: 2.1537x; 2.1537x over previous
#include <cuda_runtime.h>
#include <cuda_bf16.h>
#include <cstdint>
#include <math.h>

// GMM score via HMMA (mma.sync bf16, hi/lo 3-split) — family-neutral PTX only.
//   d[n,c] = x^T A_c x - 2 b_c^T x + k_c,  b_c = A_c m_c, k_c = m_c^T b_c
//   G[n,(c,j)] = sum_k x~_k B~[(c,j),k],  x~=[x,1] (K=65 in 80-padded layout)
//   d[n,c] = sum_j x_j G[n,(c,j)] + k_c;  score = exp(sum_c w_c log d)
//
// CTA: 128 samples, 8 warps (warp = 16 rows x 128 chunk-cols), 8 chunks of 2 comps.
// 3 split-GEMMs: Xhi*Bhi + Xhi*Blo + Xlo*Bhi (lo*lo ~2^-18, dropped).

#define ROWB   176            // bytes per smem row (88 bf16) — conflict-free ldmatrix
#define HALF_B 22528          // 128 rows * 176 B (one split image)
#define CHUNK_B 45056         // hi + lo image of one B chunk

__device__ __align__(16) unsigned char g_B[8][CHUNK_B];
__device__ float g_kc[16];

__device__ __forceinline__ uint32_t smem_u32(const void* p) {
    uint32_t a;
    asm("{ .reg .u64 t; cvta.to.shared.u64 t, %1; cvt.u32.u64 %0, t; }" : "=r"(a) : "l"(p));
    return a;
}
__device__ __forceinline__ uint32_t pk(__nv_bfloat16 a, __nv_bfloat16 b) {
    __nv_bfloat162 t(a, b);
    return *reinterpret_cast<uint32_t*>(&t);
}

#define HMMA(acc, a, b0, b1)                                                  \
    asm volatile("mma.sync.aligned.m16n8k16.row.col.f32.bf16.bf16.f32 "       \
        "{%0,%1,%2,%3},{%4,%5,%6,%7},{%8,%9},{%0,%1,%2,%3};"                  \
        : "+f"((acc)[0]), "+f"((acc)[1]), "+f"((acc)[2]), "+f"((acc)[3])      \
        : "r"((a)[0]), "r"((a)[1]), "r"((a)[2]), "r"((a)[3]), "r"(b0), "r"(b1))

// ---------------- precompute: pack B~ (hi/lo, ldmatrix-ready rows) + k_c ----------------
__global__ void precomp_kernel(const float* __restrict__ A, const float* __restrict__ Mn) {
    const int nth = gridDim.x * blockDim.x;
    for (int idx = blockIdx.x * blockDim.x + threadIdx.x; idx < 8 * 128 * 88; idx += nth) {
        const int chunk = idx / (128 * 88);
        const int rem   = idx % (128 * 88);
        const int row   = rem / 88;          // chunk-local output col (comp parity * 64 + j)
        const int k     = rem % 88;
        const int comp  = chunk * 2 + (row >> 6);
        const int j     = row & 63;
        float v = 0.0f;
        if (k < 64) {
            v = A[comp * 4096 + j * 64 + k];
        } else if (k == 64) {
            const float* Ar = A + comp * 4096 + j * 64;
            const float* mr = Mn + comp * 64;
            float s0 = 0, s1 = 0, s2 = 0, s3 = 0;
            #pragma unroll
            for (int t = 0; t < 64; t += 4) {
                s0 = fmaf(Ar[t+0], mr[t+0], s0); s1 = fmaf(Ar[t+1], mr[t+1], s1);
                s2 = fmaf(Ar[t+2], mr[t+2], s2); s3 = fmaf(Ar[t+3], mr[t+3], s3);
            }
            v = -2.0f * ((s0 + s1) + (s2 + s3));
        }
        __nv_bfloat16 hi = __float2bfloat16(v);
        __nv_bfloat16 lo = __float2bfloat16(v - __bfloat162float(hi));
        *(__nv_bfloat16*)(g_B[chunk] + row * ROWB + k * 2)          = hi;
        *(__nv_bfloat16*)(g_B[chunk] + HALF_B + row * ROWB + k * 2) = lo;
    }
    if (blockIdx.x == 0 && threadIdx.x < 16) {
        const int c = threadIdx.x;
        const float* Ac = A + c * 4096;
        const float* mc = Mn + c * 64;
        float acc = 0.0f;
        for (int j = 0; j < 64; j++) {
            const float* Ar = Ac + j * 64;
            float s0 = 0, s1 = 0, s2 = 0, s3 = 0;
            #pragma unroll
            for (int t = 0; t < 64; t += 4) {
                s0 = fmaf(Ar[t+0], mc[t+0], s0); s1 = fmaf(Ar[t+1], mc[t+1], s1);
                s2 = fmaf(Ar[t+2], mc[t+2], s2); s3 = fmaf(Ar[t+3], mc[t+3], s3);
            }
            acc = fmaf(mc[j], (s0 + s1) + (s2 + s3), acc);
        }
        g_kc[c] = acc;
    }
}

// ---------------- main kernel ----------------
// smem: [0, HALF_B) Xhi | [HALF_B, 2H) Xlo | [2H, 2H+CH) Bbuf0 | [.., +CH) Bbuf1 | 128B w/kc
#define SM_B0  (2 * HALF_B)
#define SM_WKC (2 * HALF_B + 2 * CHUNK_B)
#define SMEM_BYTES (SM_WKC + 128)

__global__ void __launch_bounds__(256, 1)
gmm_hmma_kernel(const float* __restrict__ X, const float* __restrict__ W,
                float* __restrict__ out, int N)
{
    extern __shared__ unsigned char smem[];
    const uint32_t sb = smem_u32(smem);
    const int tid  = threadIdx.x;
    const int wid  = tid >> 5;
    const int lane = tid & 31;
    const int base = blockIdx.x * 128;

    // prefetch B chunk 0 (overlaps with X staging)
    {
        size_t gsrc = __cvta_generic_to_global(g_B[0]);
        #pragma unroll
        for (int i = 0; i < 11; i++) {
            int o = (i * 256 + tid) * 16;
            asm volatile("cp.async.cg.shared.global [%0], [%1], 16;"
                         :: "r"(sb + SM_B0 + o), "l"(gsrc + o));
        }
        asm volatile("cp.async.commit_group;");
    }
    if (tid < 16) {
        *(float*)(smem + SM_WKC + 4 * tid)      = W[tid];
        *(float*)(smem + SM_WKC + 64 + 4 * tid) = g_kc[tid];
    }
    // zero X hi/lo images (covers aug col + K padding)
    {
        uint4 z = make_uint4(0, 0, 0, 0);
        #pragma unroll
        for (int i = tid; i < 2 * HALF_B / 16; i += 256) ((uint4*)smem)[i] = z;
    }
    __syncthreads();

    // stage X~: row = tid>>1, half = tid&1 handles 32 cols; col 64 = 1.0
    {
        const int row = tid >> 1, half = tid & 1;
        const float4* xg = (const float4*)(X + (size_t)(base + row) * 64 + half * 32);
        unsigned char* rp = smem + row * ROWB + half * 64;
        #pragma unroll
        for (int q = 0; q < 8; q++) {
            float4 v = xg[q];
            __nv_bfloat16 h0 = __float2bfloat16(v.x), h1 = __float2bfloat16(v.y);
            __nv_bfloat16 h2 = __float2bfloat16(v.z), h3 = __float2bfloat16(v.w);
            __nv_bfloat16 l0 = __float2bfloat16(v.x - __bfloat162float(h0));
            __nv_bfloat16 l1 = __float2bfloat16(v.y - __bfloat162float(h1));
            __nv_bfloat16 l2 = __float2bfloat16(v.z - __bfloat162float(h2));
            __nv_bfloat16 l3 = __float2bfloat16(v.w - __bfloat162float(h3));
            *(uint2*)(rp + q * 8)          = make_uint2(pk(h0, h1), pk(h2, h3));
            *(uint2*)(rp + HALF_B + q * 8) = make_uint2(pk(l0, l1), pk(l2, l3));
        }
        if (half == 0)
            *(__nv_bfloat16*)(smem + row * ROWB + 128) = __float2bfloat16(1.0f);
    }
    __syncthreads();

    // A-fragments for this warp's 16 rows, all 5 K-steps, hi and lo (reused all chunks)
    uint32_t Ahi[5][4], Alo[5][4];
    {
        const int arow = wid * 16 + ((lane >> 3) & 1) * 8 + (lane & 7);
        const uint32_t coff = (lane >> 4) * 16;
        #pragma unroll
        for (int s = 0; s < 5; s++) {
            uint32_t ah = sb + arow * ROWB + coff + s * 32;
            asm volatile("ldmatrix.sync.aligned.m8n8.x4.shared.b16 {%0,%1,%2,%3}, [%4];"
                : "=r"(Ahi[s][0]), "=r"(Ahi[s][1]), "=r"(Ahi[s][2]), "=r"(Ahi[s][3]) : "r"(ah));
            asm volatile("ldmatrix.sync.aligned.m8n8.x4.shared.b16 {%0,%1,%2,%3}, [%4];"
                : "=r"(Alo[s][0]), "=r"(Alo[s][1]), "=r"(Alo[s][2]), "=r"(Alo[s][3])
                : "r"(ah + HALF_B));
        }
    }
    // epilogue x-weights (chunk-invariant): rows r0, r0+8; j = t*8 + 2*(lane&3) + e
    float wx[2][16];
    {
        const int r0 = wid * 16 + (lane >> 2);
        #pragma unroll
        for (int rh = 0; rh < 2; rh++) {
            const int r = r0 + rh * 8;
            #pragma unroll
            for (int t = 0; t < 8; t++) {
                #pragma unroll
                for (int e = 0; e < 2; e++) {
                    const int j = t * 8 + 2 * (lane & 3) + e;
                    float h = __bfloat162float(*(__nv_bfloat16*)(smem + r * ROWB + j * 2));
                    float l = __bfloat162float(*(__nv_bfloat16*)(smem + HALF_B + r * ROWB + j * 2));
                    wx[rh][t * 2 + e] = h + l;
                }
            }
        }
    }

    float la0 = 0.0f, la1 = 0.0f;

    for (int c = 0; c < 8; c++) {
        if (c < 7) {
            size_t gsrc = __cvta_generic_to_global(g_B[c + 1]);
            uint32_t dst = sb + SM_B0 + ((c + 1) & 1) * CHUNK_B;
            #pragma unroll
            for (int i = 0; i < 11; i++) {
                int o = (i * 256 + tid) * 16;
                asm volatile("cp.async.cg.shared.global [%0], [%1], 16;"
                             :: "r"(dst + o), "l"(gsrc + o));
            }
            asm volatile("cp.async.commit_group;");
            asm volatile("cp.async.wait_group 1;");
        } else {
            asm volatile("cp.async.wait_group 0;");
        }
        __syncthreads();

        const uint32_t Bb = sb + SM_B0 + (c & 1) * CHUNK_B
                          + (lane & 7) * ROWB + ((lane >> 3) & 1) * 16;
        float acc[16][4];
        #pragma unroll
        for (int t = 0; t < 16; t++) { acc[t][0]=0.f; acc[t][1]=0.f; acc[t][2]=0.f; acc[t][3]=0.f; }

        #pragma unroll
        for (int t = 0; t < 16; t++) {
            #pragma unroll
            for (int s = 0; s < 5; s++) {
                uint32_t bh0, bh1, bl0, bl1;
                const uint32_t ab = Bb + t * (8 * ROWB) + s * 32;
                asm volatile("ldmatrix.sync.aligned.m8n8.x2.shared.b16 {%0,%1}, [%2];"
                             : "=r"(bh0), "=r"(bh1) : "r"(ab));
                asm volatile("ldmatrix.sync.aligned.m8n8.x2.shared.b16 {%0,%1}, [%2];"
                             : "=r"(bl0), "=r"(bl1) : "r"(ab + HALF_B));
                HMMA(acc[t], Ahi[s], bh0, bh1);
                HMMA(acc[t], Ahi[s], bl0, bl1);
                HMMA(acc[t], Alo[s], bh0, bh1);
            }
        }

        // epilogue: d = sum_j x_j G_j + k_c  (quad-split over lanes, bfly reduce)
        float p00 = 0, p01 = 0, p10 = 0, p11 = 0;
        #pragma unroll
        for (int t = 0; t < 16; t++) {
            const int tp = t & 7;
            const float w00 = wx[0][tp*2], w01 = wx[0][tp*2+1];
            const float w10 = wx[1][tp*2], w11 = wx[1][tp*2+1];
            if (t < 8) {
                p00 = fmaf(w00, acc[t][0], p00); p00 = fmaf(w01, acc[t][1], p00);
                p10 = fmaf(w10, acc[t][2], p10); p10 = fmaf(w11, acc[t][3], p10);
            } else {
                p01 = fmaf(w00, acc[t][0], p01); p01 = fmaf(w01, acc[t][1], p01);
                p11 = fmaf(w10, acc[t][2], p11); p11 = fmaf(w11, acc[t][3], p11);
            }
        }
        p00 += __shfl_xor_sync(0xFFFFFFFFu, p00, 1); p00 += __shfl_xor_sync(0xFFFFFFFFu, p00, 2);
        p01 += __shfl_xor_sync(0xFFFFFFFFu, p01, 1); p01 += __shfl_xor_sync(0xFFFFFFFFu, p01, 2);
        p10 += __shfl_xor_sync(0xFFFFFFFFu, p10, 1); p10 += __shfl_xor_sync(0xFFFFFFFFu, p10, 2);
        p11 += __shfl_xor_sync(0xFFFFFFFFu, p11, 1); p11 += __shfl_xor_sync(0xFFFFFFFFu, p11, 2);

        const float w0 = *(float*)(smem + SM_WKC + 8 * c);
        const float w1 = *(float*)(smem + SM_WKC + 8 * c + 4);
        const float k0 = *(float*)(smem + SM_WKC + 64 + 8 * c);
        const float k1 = *(float*)(smem + SM_WKC + 64 + 8 * c + 4);
        la0 += w0 * __logf(p00 + k0) + w1 * __logf(p01 + k1);
        la1 += w0 * __logf(p10 + k0) + w1 * __logf(p11 + k1);

        __syncthreads();   // all warps done with buf (c&1) before it is re-prefetched
    }

    if ((lane & 3) == 0) {
        const int r0 = wid * 16 + (lane >> 2);
        out[base + r0]     = __expf(la0);
        out[base + r0 + 8] = __expf(la1);
    }
}

// ---------------- launch ----------------
extern "C" void kernel_launch(void* const* d_in, const int* in_sizes, int n_in,
                              void* d_out, int out_size)
{
    const float* X     = (const float*)d_in[0];   // [N, 64]
    const float* Ainv  = (const float*)d_in[1];   // [16, 64, 64]
    const float* Means = (const float*)d_in[2];   // [16, 64]
    const float* W     = (const float*)d_in[3];   // [16]
    float* out = (float*)d_out;

    const int N = in_sizes[0] / 64;

    cudaFuncSetAttribute(gmm_hmma_kernel, cudaFuncAttributeMaxDynamicSharedMemorySize, SMEM_BYTES);

    precomp_kernel<<<64, 128>>>(Ainv, Means);
    gmm_hmma_kernel<<<N / 128, 256, SMEM_BYTES>>>(X, W, out, N);
}

// round 6
// speedup vs baseline: 3.8162x; 1.7719x over previous
#include <cuda_runtime.h>
#include <cuda_bf16.h>
#include <cstdint>
#include <math.h>

// GMM score via HMMA (mma.sync bf16, hi/lo 3-split), K=64 GEMM + epilogue linear term.
//   G[n,(c,j)] = sum_k A_c[j,k] x_k   (uncentered, K=64)
//   d[n,c] = sum_j x_j G_j  - 2 b_c.x + k_c,   b_c = A_c m_c, k_c = m_c^T b_c
//   score  = exp(sum_c w_c log d)
// CTA: 128 samples, 8 warps (warp = 16 rows x 128 chunk-cols), 8 chunks of 2 comps.
// 3 split-GEMMs: Xhi*Bhi + Xhi*Blo + Xlo*Bhi.

#define ROWB    144           // bytes per smem row (72 bf16, 64 used) — conflict-free ldmatrix
#define HALF_X  18432         // 128 rows * 144
#define HALF_BB 18432
#define CHUNK_B 36864         // hi + lo image of one B chunk

__device__ __align__(16) unsigned char g_B[8][CHUNK_B];
__device__ __align__(16) float g_bm2[1024];   // -2 * b_c[j],  [c*64 + j]
__device__ float g_kc[16];

__device__ __forceinline__ uint32_t smem_u32(const void* p) {
    uint32_t a;
    asm("{ .reg .u64 t; cvta.to.shared.u64 t, %1; cvt.u32.u64 %0, t; }" : "=r"(a) : "l"(p));
    return a;
}
__device__ __forceinline__ uint32_t pk(__nv_bfloat16 a, __nv_bfloat16 b) {
    __nv_bfloat162 t(a, b);
    return *reinterpret_cast<uint32_t*>(&t);
}

#define HMMA(acc, a, b0, b1)                                                  \
    asm volatile("mma.sync.aligned.m16n8k16.row.col.f32.bf16.bf16.f32 "       \
        "{%0,%1,%2,%3},{%4,%5,%6,%7},{%8,%9},{%0,%1,%2,%3};"                  \
        : "+f"((acc)[0]), "+f"((acc)[1]), "+f"((acc)[2]), "+f"((acc)[3])      \
        : "r"((a)[0]), "r"((a)[1]), "r"((a)[2]), "r"((a)[3]), "r"(b0), "r"(b1))

// ---------------- precomp 1: pack B hi/lo (vectorized) + b vectors ----------------
__global__ void precomp1(const float* __restrict__ A, const float* __restrict__ Mn) {
    if (blockIdx.x < 128) {
        // pack: one k-pair per thread, 32-bit stores
        const int idx   = blockIdx.x * 256 + threadIdx.x;   // 0..32767
        const int chunk = idx >> 12;
        const int rem   = idx & 4095;
        const int row   = rem >> 5;     // chunk-local col (par*64 + j)
        const int kp    = rem & 31;
        const int comp  = chunk * 2 + (row >> 6);
        const int j     = row & 63;
        const float2 v = *(const float2*)(A + comp * 4096 + j * 64 + kp * 2);
        __nv_bfloat16 h0 = __float2bfloat16(v.x), h1 = __float2bfloat16(v.y);
        __nv_bfloat16 l0 = __float2bfloat16(v.x - __bfloat162float(h0));
        __nv_bfloat16 l1 = __float2bfloat16(v.y - __bfloat162float(h1));
        *(uint32_t*)(g_B[chunk] + row * ROWB + kp * 4)           = pk(h0, h1);
        *(uint32_t*)(g_B[chunk] + HALF_BB + row * ROWB + kp * 4) = pk(l0, l1);
    } else {
        // b_c[j] = A_c[j,:] . m_c  (one thread per (c,j), float4 loads)
        const int bi = (blockIdx.x - 128) * 256 + threadIdx.x;  // 0..1023
        const int c = bi >> 6, j = bi & 63;
        const float4* Ar = (const float4*)(A + c * 4096 + j * 64);
        const float4* mr = (const float4*)(Mn + c * 64);
        float s0 = 0, s1 = 0, s2 = 0, s3 = 0;
        #pragma unroll
        for (int t = 0; t < 16; t++) {
            float4 a = Ar[t], m = mr[t];
            s0 = fmaf(a.x, m.x, s0); s1 = fmaf(a.y, m.y, s1);
            s2 = fmaf(a.z, m.z, s2); s3 = fmaf(a.w, m.w, s3);
        }
        g_bm2[bi] = -2.0f * ((s0 + s1) + (s2 + s3));
    }
}

// ---------------- precomp 2: k_c = m_c^T b_c ----------------
__global__ void precomp2(const float* __restrict__ Mn) {
    const int c = threadIdx.x;
    if (c < 16) {
        float acc = 0.0f;
        #pragma unroll
        for (int j = 0; j < 64; j++)
            acc = fmaf(Mn[c * 64 + j], -0.5f * g_bm2[c * 64 + j], acc);
        g_kc[c] = acc;
    }
}

// ---------------- main kernel ----------------
// smem: Xhi [0,18432) | Xlo [18432, 36864) | 3 x B buf (36864 each) | bm2 4KB | w/kc 128B
#define SM_B0  36864
#define SM_BM  (36864 + 3 * CHUNK_B)       // 147456
#define SM_WKC (SM_BM + 4096)              // 151552
#define SMEM_BYTES (SM_WKC + 128)          // 151680

__global__ void __launch_bounds__(256, 1)
gmm_hmma_kernel(const float* __restrict__ X, const float* __restrict__ W,
                float* __restrict__ out, int N)
{
    extern __shared__ unsigned char smem[];
    const uint32_t sb = smem_u32(smem);
    const int tid  = threadIdx.x;
    const int wid  = tid >> 5;
    const int lane = tid & 31;
    const int base = blockIdx.x * 128;

    // prefetch B chunks 0 and 1 (one commit-group each)
    #pragma unroll
    for (int pc = 0; pc < 2; pc++) {
        size_t gsrc = __cvta_generic_to_global(g_B[pc]);
        const uint32_t dst = sb + SM_B0 + pc * CHUNK_B;
        #pragma unroll
        for (int i = 0; i < 9; i++) {                 // 9*256*16 = 36864
            int o = (i * 256 + tid) * 16;
            asm volatile("cp.async.cg.shared.global [%0], [%1], 16;"
                         :: "r"(dst + o), "l"(gsrc + o));
        }
        asm volatile("cp.async.commit_group;");
    }
    if (tid < 16) {
        *(float*)(smem + SM_WKC + 4 * tid)      = W[tid];
        *(float*)(smem + SM_WKC + 64 + 4 * tid) = g_kc[tid];
    }
    ((float4*)(smem + SM_BM))[tid] = ((const float4*)g_bm2)[tid];  // 256*16B = 4KB

    // stage X hi/lo: row = tid>>1, half = tid&1 covers 32 cols
    {
        const int row = tid >> 1, half = tid & 1;
        const float4* xg = (const float4*)(X + (size_t)(base + row) * 64 + half * 32);
        unsigned char* rp = smem + row * ROWB + half * 64;
        #pragma unroll
        for (int q = 0; q < 8; q++) {
            float4 v = xg[q];
            __nv_bfloat16 h0 = __float2bfloat16(v.x), h1 = __float2bfloat16(v.y);
            __nv_bfloat16 h2 = __float2bfloat16(v.z), h3 = __float2bfloat16(v.w);
            __nv_bfloat16 l0 = __float2bfloat16(v.x - __bfloat162float(h0));
            __nv_bfloat16 l1 = __float2bfloat16(v.y - __bfloat162float(h1));
            __nv_bfloat16 l2 = __float2bfloat16(v.z - __bfloat162float(h2));
            __nv_bfloat16 l3 = __float2bfloat16(v.w - __bfloat162float(h3));
            *(uint2*)(rp + q * 8)          = make_uint2(pk(h0, h1), pk(h2, h3));
            *(uint2*)(rp + HALF_X + q * 8) = make_uint2(pk(l0, l1), pk(l2, l3));
        }
    }
    __syncthreads();

    // A-fragments (this warp's 16 rows, 4 K-steps, hi+lo) — reused across all chunks
    uint32_t Ahi[4][4], Alo[4][4];
    {
        const int arow = wid * 16 + ((lane >> 3) & 1) * 8 + (lane & 7);
        const uint32_t coff = (lane >> 4) * 16;
        #pragma unroll
        for (int s = 0; s < 4; s++) {
            uint32_t ah = sb + arow * ROWB + coff + s * 32;
            asm volatile("ldmatrix.sync.aligned.m8n8.x4.shared.b16 {%0,%1,%2,%3}, [%4];"
                : "=r"(Ahi[s][0]), "=r"(Ahi[s][1]), "=r"(Ahi[s][2]), "=r"(Ahi[s][3]) : "r"(ah));
            asm volatile("ldmatrix.sync.aligned.m8n8.x4.shared.b16 {%0,%1,%2,%3}, [%4];"
                : "=r"(Alo[s][0]), "=r"(Alo[s][1]), "=r"(Alo[s][2]), "=r"(Alo[s][3])
                : "r"(ah + HALF_X));
        }
    }
    // epilogue x-weights (chunk-invariant): rows r0, r0+8; j = (i>>1)*8 + 2*(lane&3) + (i&1)
    float wx[2][16];
    {
        const int r0 = wid * 16 + (lane >> 2);
        #pragma unroll
        for (int rh = 0; rh < 2; rh++) {
            const int r = r0 + rh * 8;
            #pragma unroll
            for (int i = 0; i < 16; i++) {
                const int j = (i >> 1) * 8 + 2 * (lane & 3) + (i & 1);
                float h = __bfloat162float(*(__nv_bfloat16*)(smem + r * ROWB + j * 2));
                float l = __bfloat162float(*(__nv_bfloat16*)(smem + HALF_X + r * ROWB + j * 2));
                wx[rh][i] = h + l;
            }
        }
    }

    float la0 = 0.0f, la1 = 0.0f;

    for (int c = 0; c < 8; c++) {
        if (c + 2 < 8) {
            size_t gsrc = __cvta_generic_to_global(g_B[c + 2]);
            const uint32_t dst = sb + SM_B0 + ((c + 2) % 3) * CHUNK_B;
            #pragma unroll
            for (int i = 0; i < 9; i++) {
                int o = (i * 256 + tid) * 16;
                asm volatile("cp.async.cg.shared.global [%0], [%1], 16;"
                             :: "r"(dst + o), "l"(gsrc + o));
            }
        }
        asm volatile("cp.async.commit_group;");     // possibly-empty group keeps count uniform
        asm volatile("cp.async.wait_group 2;");
        __syncthreads();

        // B base: rows = n within pair-tile, 16B k-halves, second n-tile at +8 rows
        const uint32_t Bb = sb + SM_B0 + (c % 3) * CHUNK_B
                          + ((lane >> 4) * 8 + (lane & 7)) * ROWB + ((lane >> 3) & 1) * 16;
        float acc[16][4];
        #pragma unroll
        for (int t = 0; t < 16; t++) { acc[t][0]=0.f; acc[t][1]=0.f; acc[t][2]=0.f; acc[t][3]=0.f; }

        #pragma unroll
        for (int t2 = 0; t2 < 8; t2++) {
            #pragma unroll
            for (int s = 0; s < 4; s++) {
                uint32_t bh0, bh1, bh2, bh3, bl0, bl1, bl2, bl3;
                const uint32_t ab = Bb + t2 * (16 * ROWB) + s * 32;
                asm volatile("ldmatrix.sync.aligned.m8n8.x4.shared.b16 {%0,%1,%2,%3}, [%4];"
                             : "=r"(bh0), "=r"(bh1), "=r"(bh2), "=r"(bh3) : "r"(ab));
                asm volatile("ldmatrix.sync.aligned.m8n8.x4.shared.b16 {%0,%1,%2,%3}, [%4];"
                             : "=r"(bl0), "=r"(bl1), "=r"(bl2), "=r"(bl3) : "r"(ab + HALF_BB));
                HMMA(acc[2*t2],   Ahi[s], bh0, bh1);
                HMMA(acc[2*t2+1], Ahi[s], bh2, bh3);
                HMMA(acc[2*t2],   Ahi[s], bl0, bl1);
                HMMA(acc[2*t2+1], Ahi[s], bl2, bl3);
                HMMA(acc[2*t2],   Alo[s], bh0, bh1);
                HMMA(acc[2*t2+1], Alo[s], bh2, bh3);
            }
        }

        // epilogue: p = sum_j x_j G_j  + sum_j x_j * (-2 b_j)  (the latter is chunk-constant)
        const float* bm0 = (const float*)(smem + SM_BM) + (2 * c) * 64;
        const float* bm1 = bm0 + 64;
        float p00 = 0, p01 = 0, p10 = 0, p11 = 0;
        #pragma unroll
        for (int i = 0; i < 16; i++) {
            const int j = (i >> 1) * 8 + 2 * (lane & 3) + (i & 1);
            const float b0 = bm0[j], b1 = bm1[j];
            p00 = fmaf(wx[0][i], b0, p00); p01 = fmaf(wx[0][i], b1, p01);
            p10 = fmaf(wx[1][i], b0, p10); p11 = fmaf(wx[1][i], b1, p11);
        }
        #pragma unroll
        for (int t = 0; t < 16; t++) {
            const int tp = t & 7;
            const float w00 = wx[0][tp*2], w01 = wx[0][tp*2+1];
            const float w10 = wx[1][tp*2], w11 = wx[1][tp*2+1];
            if (t < 8) {
                p00 = fmaf(w00, acc[t][0], p00); p00 = fmaf(w01, acc[t][1], p00);
                p10 = fmaf(w10, acc[t][2], p10); p10 = fmaf(w11, acc[t][3], p10);
            } else {
                p01 = fmaf(w00, acc[t][0], p01); p01 = fmaf(w01, acc[t][1], p01);
                p11 = fmaf(w10, acc[t][2], p11); p11 = fmaf(w11, acc[t][3], p11);
            }
        }
        p00 += __shfl_xor_sync(0xFFFFFFFFu, p00, 1); p00 += __shfl_xor_sync(0xFFFFFFFFu, p00, 2);
        p01 += __shfl_xor_sync(0xFFFFFFFFu, p01, 1); p01 += __shfl_xor_sync(0xFFFFFFFFu, p01, 2);
        p10 += __shfl_xor_sync(0xFFFFFFFFu, p10, 1); p10 += __shfl_xor_sync(0xFFFFFFFFu, p10, 2);
        p11 += __shfl_xor_sync(0xFFFFFFFFu, p11, 1); p11 += __shfl_xor_sync(0xFFFFFFFFu, p11, 2);

        const float w0 = *(float*)(smem + SM_WKC + 8 * c);
        const float w1 = *(float*)(smem + SM_WKC + 8 * c + 4);
        const float k0 = *(float*)(smem + SM_WKC + 64 + 8 * c);
        const float k1 = *(float*)(smem + SM_WKC + 64 + 8 * c + 4);
        la0 += w0 * __logf(p00 + k0) + w1 * __logf(p01 + k1);
        la1 += w0 * __logf(p10 + k0) + w1 * __logf(p11 + k1);

        __syncthreads();   // all warps done reading buf (c%3) before it is re-prefetched
    }

    if ((lane & 3) == 0) {
        const int r0 = wid * 16 + (lane >> 2);
        out[base + r0]     = __expf(la0);
        out[base + r0 + 8] = __expf(la1);
    }
}

// ---------------- launch ----------------
extern "C" void kernel_launch(void* const* d_in, const int* in_sizes, int n_in,
                              void* d_out, int out_size)
{
    const float* X     = (const float*)d_in[0];   // [N, 64]
    const float* Ainv  = (const float*)d_in[1];   // [16, 64, 64]
    const float* Means = (const float*)d_in[2];   // [16, 64]
    const float* W     = (const float*)d_in[3];   // [16]
    float* out = (float*)d_out;

    const int N = in_sizes[0] / 64;

    cudaFuncSetAttribute(gmm_hmma_kernel, cudaFuncAttributeMaxDynamicSharedMemorySize, SMEM_BYTES);

    precomp1<<<132, 256>>>(Ainv, Means);
    precomp2<<<1, 32>>>(Means);
    gmm_hmma_kernel<<<N / 128, 256, SMEM_BYTES>>>(X, W, out, N);
}

// round 7
// speedup vs baseline: 4.7861x; 1.2542x over previous
#include <cuda_runtime.h>
#include <cuda_bf16.h>
#include <cstdint>
#include <math.h>

// GMM score via HMMA (mma.sync bf16), symmetry-exploiting 2-split GEMM.
//   G[n,(c,j)] = sum_k A_c[j,k] xh_k        (GEMM on xh only; B in hi+lo splits)
//   x^T A x    = sum_j (xh+2*xl)_j G_j + xl^T A xl (dropped, ~2^-18)
//   d[n,c]     = sum_j u_j G_j - 2 b_c.x + k_c,  u = xh+2xl, x-dot exact via xh+xl
//   score      = exp(sum_c w_c log d)
// CTA: 128 samples, 8 warps (warp = 16 rows x 128 chunk-cols), 8 chunks of 2 comps.

#define ROWB    144           // bytes per smem row (72 bf16, 64 used) — conflict-free ldmatrix
#define HALF_X  18432         // 128 rows * 144
#define HALF_BB 18432
#define CHUNK_B 36864         // hi + lo image of one B chunk

__device__ __align__(16) unsigned char g_B[8][CHUNK_B];
__device__ __align__(16) float g_bm2[1024];   // -2 * b_c[j],  [c*64 + j]
__device__ float g_kc[16];

__device__ __forceinline__ uint32_t smem_u32(const void* p) {
    uint32_t a;
    asm("{ .reg .u64 t; cvta.to.shared.u64 t, %1; cvt.u32.u64 %0, t; }" : "=r"(a) : "l"(p));
    return a;
}
__device__ __forceinline__ uint32_t pk(__nv_bfloat16 a, __nv_bfloat16 b) {
    __nv_bfloat162 t(a, b);
    return *reinterpret_cast<uint32_t*>(&t);
}

#define HMMA(acc, a, b0, b1)                                                  \
    asm volatile("mma.sync.aligned.m16n8k16.row.col.f32.bf16.bf16.f32 "       \
        "{%0,%1,%2,%3},{%4,%5,%6,%7},{%8,%9},{%0,%1,%2,%3};"                  \
        : "+f"((acc)[0]), "+f"((acc)[1]), "+f"((acc)[2]), "+f"((acc)[3])      \
        : "r"((a)[0]), "r"((a)[1]), "r"((a)[2]), "r"((a)[3]), "r"(b0), "r"(b1))

// ---------------- precomp 1: pack B hi/lo (vectorized) + b vectors ----------------
__global__ void precomp1(const float* __restrict__ A, const float* __restrict__ Mn) {
    if (blockIdx.x < 128) {
        const int idx   = blockIdx.x * 256 + threadIdx.x;   // 0..32767
        const int chunk = idx >> 12;
        const int rem   = idx & 4095;
        const int row   = rem >> 5;     // chunk-local col (par*64 + j)
        const int kp    = rem & 31;
        const int comp  = chunk * 2 + (row >> 6);
        const int j     = row & 63;
        const float2 v = *(const float2*)(A + comp * 4096 + j * 64 + kp * 2);
        __nv_bfloat16 h0 = __float2bfloat16(v.x), h1 = __float2bfloat16(v.y);
        __nv_bfloat16 l0 = __float2bfloat16(v.x - __bfloat162float(h0));
        __nv_bfloat16 l1 = __float2bfloat16(v.y - __bfloat162float(h1));
        *(uint32_t*)(g_B[chunk] + row * ROWB + kp * 4)           = pk(h0, h1);
        *(uint32_t*)(g_B[chunk] + HALF_BB + row * ROWB + kp * 4) = pk(l0, l1);
    } else {
        // b_c[j] = A_c[j,:] . m_c
        const int bi = (blockIdx.x - 128) * 256 + threadIdx.x;  // 0..1023
        const int c = bi >> 6, j = bi & 63;
        const float4* Ar = (const float4*)(A + c * 4096 + j * 64);
        const float4* mr = (const float4*)(Mn + c * 64);
        float s0 = 0, s1 = 0, s2 = 0, s3 = 0;
        #pragma unroll
        for (int t = 0; t < 16; t++) {
            float4 a = Ar[t], m = mr[t];
            s0 = fmaf(a.x, m.x, s0); s1 = fmaf(a.y, m.y, s1);
            s2 = fmaf(a.z, m.z, s2); s3 = fmaf(a.w, m.w, s3);
        }
        g_bm2[bi] = -2.0f * ((s0 + s1) + (s2 + s3));
    }
}

// ---------------- precomp 2: k_c = m_c^T b_c ----------------
__global__ void precomp2(const float* __restrict__ Mn) {
    const int c = threadIdx.x;
    if (c < 16) {
        float acc = 0.0f;
        #pragma unroll
        for (int j = 0; j < 64; j++)
            acc = fmaf(Mn[c * 64 + j], -0.5f * g_bm2[c * 64 + j], acc);
        g_kc[c] = acc;
    }
}

// ---------------- main kernel ----------------
// smem: Xhi [0,18432) | Xlo [18432, 36864) | 3 x B buf (36864 each) | bm2 4KB | w/kc 128B
#define SM_B0  36864
#define SM_BM  (36864 + 3 * CHUNK_B)       // 147456
#define SM_WKC (SM_BM + 4096)              // 151552
#define SMEM_BYTES (SM_WKC + 128)          // 151680

__global__ void __launch_bounds__(256, 1)
gmm_hmma_kernel(const float* __restrict__ X, const float* __restrict__ W,
                float* __restrict__ out, int N)
{
    extern __shared__ unsigned char smem[];
    const uint32_t sb = smem_u32(smem);
    const int tid  = threadIdx.x;
    const int wid  = tid >> 5;
    const int lane = tid & 31;
    const int base = blockIdx.x * 128;

    // prefetch B chunks 0 and 1 (one commit-group each)
    #pragma unroll
    for (int pc = 0; pc < 2; pc++) {
        size_t gsrc = __cvta_generic_to_global(g_B[pc]);
        const uint32_t dst = sb + SM_B0 + pc * CHUNK_B;
        #pragma unroll
        for (int i = 0; i < 9; i++) {                 // 9*256*16 = 36864
            int o = (i * 256 + tid) * 16;
            asm volatile("cp.async.cg.shared.global [%0], [%1], 16;"
                         :: "r"(dst + o), "l"(gsrc + o));
        }
        asm volatile("cp.async.commit_group;");
    }
    if (tid < 16) {
        *(float*)(smem + SM_WKC + 4 * tid)      = W[tid];
        *(float*)(smem + SM_WKC + 64 + 4 * tid) = g_kc[tid];
    }
    ((float4*)(smem + SM_BM))[tid] = ((const float4*)g_bm2)[tid];  // 256*16B = 4KB

    // stage X hi/lo: row = tid>>1, half = tid&1 covers 32 cols
    {
        const int row = tid >> 1, half = tid & 1;
        const float4* xg = (const float4*)(X + (size_t)(base + row) * 64 + half * 32);
        unsigned char* rp = smem + row * ROWB + half * 64;
        #pragma unroll
        for (int q = 0; q < 8; q++) {
            float4 v = xg[q];
            __nv_bfloat16 h0 = __float2bfloat16(v.x), h1 = __float2bfloat16(v.y);
            __nv_bfloat16 h2 = __float2bfloat16(v.z), h3 = __float2bfloat16(v.w);
            __nv_bfloat16 l0 = __float2bfloat16(v.x - __bfloat162float(h0));
            __nv_bfloat16 l1 = __float2bfloat16(v.y - __bfloat162float(h1));
            __nv_bfloat16 l2 = __float2bfloat16(v.z - __bfloat162float(h2));
            __nv_bfloat16 l3 = __float2bfloat16(v.w - __bfloat162float(h3));
            *(uint2*)(rp + q * 8)          = make_uint2(pk(h0, h1), pk(h2, h3));
            *(uint2*)(rp + HALF_X + q * 8) = make_uint2(pk(l0, l1), pk(l2, l3));
        }
    }
    __syncthreads();

    // A-fragments: only Xhi enters the GEMM (symmetry trick folds xl into weights)
    uint32_t Ahi[4][4];
    {
        const int arow = wid * 16 + ((lane >> 3) & 1) * 8 + (lane & 7);
        const uint32_t coff = (lane >> 4) * 16;
        #pragma unroll
        for (int s = 0; s < 4; s++) {
            uint32_t ah = sb + arow * ROWB + coff + s * 32;
            asm volatile("ldmatrix.sync.aligned.m8n8.x4.shared.b16 {%0,%1,%2,%3}, [%4];"
                : "=r"(Ahi[s][0]), "=r"(Ahi[s][1]), "=r"(Ahi[s][2]), "=r"(Ahi[s][3]) : "r"(ah));
        }
    }
    // epilogue weights (chunk-invariant), j = (i>>1)*8 + 2*(lane&3) + (i&1):
    //   wx  = xh + 2*xl  -> quadratic term via symmetry
    //   wxe = xh +   xl  -> exact x for the linear (-2b.x) term
    float wx[2][16], wxe[2][16];
    {
        const int r0 = wid * 16 + (lane >> 2);
        #pragma unroll
        for (int rh = 0; rh < 2; rh++) {
            const int r = r0 + rh * 8;
            #pragma unroll
            for (int i = 0; i < 16; i++) {
                const int j = (i >> 1) * 8 + 2 * (lane & 3) + (i & 1);
                float h = __bfloat162float(*(__nv_bfloat16*)(smem + r * ROWB + j * 2));
                float l = __bfloat162float(*(__nv_bfloat16*)(smem + HALF_X + r * ROWB + j * 2));
                wx[rh][i]  = h + 2.0f * l;
                wxe[rh][i] = h + l;
            }
        }
    }

    float la0 = 0.0f, la1 = 0.0f;

    for (int c = 0; c < 8; c++) {
        // retire the group carrying chunk c, then one barrier: data visible to all
        // AND all warps are past their iter c-1 reads (safe to overwrite buf (c+2)%3).
        asm volatile("cp.async.wait_group 1;");
        __syncthreads();

        if (c + 2 < 8) {
            size_t gsrc = __cvta_generic_to_global(g_B[c + 2]);
            const uint32_t dst = sb + SM_B0 + ((c + 2) % 3) * CHUNK_B;
            #pragma unroll
            for (int i = 0; i < 9; i++) {
                int o = (i * 256 + tid) * 16;
                asm volatile("cp.async.cg.shared.global [%0], [%1], 16;"
                             :: "r"(dst + o), "l"(gsrc + o));
            }
        }
        asm volatile("cp.async.commit_group;");     // possibly-empty group keeps count uniform

        // B base: rows = n within pair-tile, 16B k-halves, second n-tile at +8 rows
        const uint32_t Bb = sb + SM_B0 + (c % 3) * CHUNK_B
                          + ((lane >> 4) * 8 + (lane & 7)) * ROWB + ((lane >> 3) & 1) * 16;
        float acc[16][4];
        #pragma unroll
        for (int t = 0; t < 16; t++) { acc[t][0]=0.f; acc[t][1]=0.f; acc[t][2]=0.f; acc[t][3]=0.f; }

        #pragma unroll
        for (int t2 = 0; t2 < 8; t2++) {
            #pragma unroll
            for (int s = 0; s < 4; s++) {
                uint32_t bh0, bh1, bh2, bh3, bl0, bl1, bl2, bl3;
                const uint32_t ab = Bb + t2 * (16 * ROWB) + s * 32;
                asm volatile("ldmatrix.sync.aligned.m8n8.x4.shared.b16 {%0,%1,%2,%3}, [%4];"
                             : "=r"(bh0), "=r"(bh1), "=r"(bh2), "=r"(bh3) : "r"(ab));
                asm volatile("ldmatrix.sync.aligned.m8n8.x4.shared.b16 {%0,%1,%2,%3}, [%4];"
                             : "=r"(bl0), "=r"(bl1), "=r"(bl2), "=r"(bl3) : "r"(ab + HALF_BB));
                HMMA(acc[2*t2],   Ahi[s], bh0, bh1);
                HMMA(acc[2*t2+1], Ahi[s], bh2, bh3);
                HMMA(acc[2*t2],   Ahi[s], bl0, bl1);
                HMMA(acc[2*t2+1], Ahi[s], bl2, bl3);
            }
        }

        // epilogue: p = sum_j u_j G_j + sum_j x_j * (-2 b_j)
        const float* bm0 = (const float*)(smem + SM_BM) + (2 * c) * 64;
        const float* bm1 = bm0 + 64;
        float p00 = 0, p01 = 0, p10 = 0, p11 = 0;
        #pragma unroll
        for (int i = 0; i < 16; i++) {
            const int j = (i >> 1) * 8 + 2 * (lane & 3) + (i & 1);
            const float b0 = bm0[j], b1 = bm1[j];
            p00 = fmaf(wxe[0][i], b0, p00); p01 = fmaf(wxe[0][i], b1, p01);
            p10 = fmaf(wxe[1][i], b0, p10); p11 = fmaf(wxe[1][i], b1, p11);
        }
        #pragma unroll
        for (int t = 0; t < 16; t++) {
            const int tp = t & 7;
            const float w00 = wx[0][tp*2], w01 = wx[0][tp*2+1];
            const float w10 = wx[1][tp*2], w11 = wx[1][tp*2+1];
            if (t < 8) {
                p00 = fmaf(w00, acc[t][0], p00); p00 = fmaf(w01, acc[t][1], p00);
                p10 = fmaf(w10, acc[t][2], p10); p10 = fmaf(w11, acc[t][3], p10);
            } else {
                p01 = fmaf(w00, acc[t][0], p01); p01 = fmaf(w01, acc[t][1], p01);
                p11 = fmaf(w10, acc[t][2], p11); p11 = fmaf(w11, acc[t][3], p11);
            }
        }
        p00 += __shfl_xor_sync(0xFFFFFFFFu, p00, 1); p00 += __shfl_xor_sync(0xFFFFFFFFu, p00, 2);
        p01 += __shfl_xor_sync(0xFFFFFFFFu, p01, 1); p01 += __shfl_xor_sync(0xFFFFFFFFu, p01, 2);
        p10 += __shfl_xor_sync(0xFFFFFFFFu, p10, 1); p10 += __shfl_xor_sync(0xFFFFFFFFu, p10, 2);
        p11 += __shfl_xor_sync(0xFFFFFFFFu, p11, 1); p11 += __shfl_xor_sync(0xFFFFFFFFu, p11, 2);

        const float w0 = *(float*)(smem + SM_WKC + 8 * c);
        const float w1 = *(float*)(smem + SM_WKC + 8 * c + 4);
        const float k0 = *(float*)(smem + SM_WKC + 64 + 8 * c);
        const float k1 = *(float*)(smem + SM_WKC + 64 + 8 * c + 4);
        la0 += w0 * __logf(p00 + k0) + w1 * __logf(p01 + k1);
        la1 += w0 * __logf(p10 + k0) + w1 * __logf(p11 + k1);
    }

    if ((lane & 3) == 0) {
        const int r0 = wid * 16 + (lane >> 2);
        out[base + r0]     = __expf(la0);
        out[base + r0 + 8] = __expf(la1);
    }
}

// ---------------- launch ----------------
extern "C" void kernel_launch(void* const* d_in, const int* in_sizes, int n_in,
                              void* d_out, int out_size)
{
    const float* X     = (const float*)d_in[0];   // [N, 64]
    const float* Ainv  = (const float*)d_in[1];   // [16, 64, 64]
    const float* Means = (const float*)d_in[2];   // [16, 64]
    const float* W     = (const float*)d_in[3];   // [16]
    float* out = (float*)d_out;

    const int N = in_sizes[0] / 64;

    cudaFuncSetAttribute(gmm_hmma_kernel, cudaFuncAttributeMaxDynamicSharedMemorySize, SMEM_BYTES);

    precomp1<<<132, 256>>>(Ainv, Means);
    precomp2<<<1, 32>>>(Means);
    gmm_hmma_kernel<<<N / 128, 256, SMEM_BYTES>>>(X, W, out, N);
}

// round 8
// speedup vs baseline: 5.3597x; 1.1198x over previous
#include <cuda_runtime.h>
#include <cuda_bf16.h>
#include <cstdint>
#include <math.h>

// GMM score via HMMA (mma.sync bf16), symmetry 2-split GEMM, 2 CTAs/SM.
//   G[n,(c,j)] = sum_k A_c[j,k] xh_k        (GEMM on xh only; B in hi+lo splits)
//   x^T A x    = sum_j (xh+2*xl)_j G_j  (+ xl^T A xl dropped, ~2^-18)
//   d[n,c]     = quad + sum_j (xh+xl)_j * (-2 b_c[j]) + k_c
//   score      = exp(sum_c w_c log d)
// CTA: 128 samples, 8 warps; chunk = 2 comps processed as two sequential halves
// (acc[8][4] reused) to fit 128 regs -> 2 CTAs/SM.

#define ROWB    144           // bytes per smem row (72 bf16, 64 used) — conflict-free ldmatrix
#define XHI_B   18432         // 128 rows * 144
#define HALF_BB 18432
#define CHUNK_B 36864         // hi + lo image of one B chunk

__device__ __align__(16) unsigned char g_B[8][CHUNK_B];
__device__ __align__(16) float g_bm2[1024];   // -2 * b_c[j],  [c*64 + j]
__device__ float g_kc[16];

__device__ __forceinline__ uint32_t smem_u32(const void* p) {
    uint32_t a;
    asm("{ .reg .u64 t; cvta.to.shared.u64 t, %1; cvt.u32.u64 %0, t; }" : "=r"(a) : "l"(p));
    return a;
}
__device__ __forceinline__ uint32_t pk(__nv_bfloat16 a, __nv_bfloat16 b) {
    __nv_bfloat162 t(a, b);
    return *reinterpret_cast<uint32_t*>(&t);
}

#define HMMA(acc, a, b0, b1)                                                  \
    asm volatile("mma.sync.aligned.m16n8k16.row.col.f32.bf16.bf16.f32 "       \
        "{%0,%1,%2,%3},{%4,%5,%6,%7},{%8,%9},{%0,%1,%2,%3};"                  \
        : "+f"((acc)[0]), "+f"((acc)[1]), "+f"((acc)[2]), "+f"((acc)[3])      \
        : "r"((a)[0]), "r"((a)[1]), "r"((a)[2]), "r"((a)[3]), "r"(b0), "r"(b1))

// ---------------- precomp 1: pack B hi/lo + b vectors ----------------
__global__ void precomp1(const float* __restrict__ A, const float* __restrict__ Mn) {
    if (blockIdx.x < 128) {
        const int idx   = blockIdx.x * 256 + threadIdx.x;   // 0..32767
        const int chunk = idx >> 12;
        const int rem   = idx & 4095;
        const int row   = rem >> 5;     // chunk-local col (par*64 + j)
        const int kp    = rem & 31;
        const int comp  = chunk * 2 + (row >> 6);
        const int j     = row & 63;
        const float2 v = *(const float2*)(A + comp * 4096 + j * 64 + kp * 2);
        __nv_bfloat16 h0 = __float2bfloat16(v.x), h1 = __float2bfloat16(v.y);
        __nv_bfloat16 l0 = __float2bfloat16(v.x - __bfloat162float(h0));
        __nv_bfloat16 l1 = __float2bfloat16(v.y - __bfloat162float(h1));
        *(uint32_t*)(g_B[chunk] + row * ROWB + kp * 4)           = pk(h0, h1);
        *(uint32_t*)(g_B[chunk] + HALF_BB + row * ROWB + kp * 4) = pk(l0, l1);
    } else {
        // b_c[j] = A_c[j,:] . m_c
        const int bi = (blockIdx.x - 128) * 256 + threadIdx.x;  // 0..1023
        const int c = bi >> 6, j = bi & 63;
        const float4* Ar = (const float4*)(A + c * 4096 + j * 64);
        const float4* mr = (const float4*)(Mn + c * 64);
        float s0 = 0, s1 = 0, s2 = 0, s3 = 0;
        #pragma unroll
        for (int t = 0; t < 16; t++) {
            float4 a = Ar[t], m = mr[t];
            s0 = fmaf(a.x, m.x, s0); s1 = fmaf(a.y, m.y, s1);
            s2 = fmaf(a.z, m.z, s2); s3 = fmaf(a.w, m.w, s3);
        }
        g_bm2[bi] = -2.0f * ((s0 + s1) + (s2 + s3));
    }
}

// ---------------- precomp 2: k_c = m_c^T b_c ----------------
__global__ void precomp2(const float* __restrict__ Mn) {
    const int c = threadIdx.x;
    if (c < 16) {
        float acc = 0.0f;
        #pragma unroll
        for (int j = 0; j < 64; j++)
            acc = fmaf(Mn[c * 64 + j], -0.5f * g_bm2[c * 64 + j], acc);
        g_kc[c] = acc;
    }
}

// ---------------- main kernel ----------------
// smem: Xhi [0,18432) | 2 x B buf (36864 each) | bm2 4KB | w/kc 128B
#define SM_B0  XHI_B                          // 18432
#define SM_BM  (XHI_B + 2 * CHUNK_B)          // 92160
#define SM_WKC (SM_BM + 4096)                 // 96256
#define SMEM_BYTES (SM_WKC + 128)             // 96384

__global__ void __launch_bounds__(256, 2)
gmm_hmma_kernel(const float* __restrict__ X, const float* __restrict__ W,
                float* __restrict__ out, int N)
{
    extern __shared__ unsigned char smem[];
    const uint32_t sb = smem_u32(smem);
    const int tid  = threadIdx.x;
    const int wid  = tid >> 5;
    const int lane = tid & 31;
    const int base = blockIdx.x * 128;

    // prefetch B chunk 0
    {
        size_t gsrc = __cvta_generic_to_global(g_B[0]);
        const uint32_t dst = sb + SM_B0;
        #pragma unroll
        for (int i = 0; i < 9; i++) {                 // 9*256*16 = 36864
            int o = (i * 256 + tid) * 16;
            asm volatile("cp.async.cg.shared.global [%0], [%1], 16;"
                         :: "r"(dst + o), "l"(gsrc + o));
        }
        asm volatile("cp.async.commit_group;");
    }
    if (tid < 16) {
        *(float*)(smem + SM_WKC + 4 * tid)      = W[tid];
        *(float*)(smem + SM_WKC + 64 + 4 * tid) = g_kc[tid];
    }
    ((float4*)(smem + SM_BM))[tid] = ((const float4*)g_bm2)[tid];  // 4KB

    // stage Xhi only: row = tid>>1, half = tid&1 covers 32 cols
    {
        const int row = tid >> 1, half = tid & 1;
        const float4* xg = (const float4*)(X + (size_t)(base + row) * 64 + half * 32);
        unsigned char* rp = smem + row * ROWB + half * 64;
        #pragma unroll
        for (int q = 0; q < 8; q++) {
            float4 v = xg[q];
            *(uint2*)(rp + q * 8) = make_uint2(
                pk(__float2bfloat16(v.x), __float2bfloat16(v.y)),
                pk(__float2bfloat16(v.z), __float2bfloat16(v.w)));
        }
    }

    // epilogue weights straight from global X (no Xlo smem image):
    //   wx  = xh + 2*xl (fp32), xlp = xl packed bf16 (exact) -> wxe = wx - xl
    float    wx[2][16];
    uint32_t xlp[2][8];
    {
        const int r0 = wid * 16 + (lane >> 2);
        #pragma unroll
        for (int rh = 0; rh < 2; rh++) {
            const float* xr = X + (size_t)(base + r0 + rh * 8) * 64 + 2 * (lane & 3);
            #pragma unroll
            for (int q = 0; q < 8; q++) {
                float2 v = *(const float2*)(xr + q * 8);
                __nv_bfloat16 h0 = __float2bfloat16(v.x), h1 = __float2bfloat16(v.y);
                float l0 = v.x - __bfloat162float(h0);
                float l1 = v.y - __bfloat162float(h1);
                wx[rh][2*q]   = __bfloat162float(h0) + 2.0f * l0;
                wx[rh][2*q+1] = __bfloat162float(h1) + 2.0f * l1;
                xlp[rh][q] = pk(__float2bfloat16(l0), __float2bfloat16(l1));
            }
        }
    }
    __syncthreads();

    // A-fragments (Xhi only)
    uint32_t Ahi[4][4];
    {
        const int arow = wid * 16 + ((lane >> 3) & 1) * 8 + (lane & 7);
        const uint32_t coff = (lane >> 4) * 16;
        #pragma unroll
        for (int s = 0; s < 4; s++) {
            uint32_t ah = sb + arow * ROWB + coff + s * 32;
            asm volatile("ldmatrix.sync.aligned.m8n8.x4.shared.b16 {%0,%1,%2,%3}, [%4];"
                : "=r"(Ahi[s][0]), "=r"(Ahi[s][1]), "=r"(Ahi[s][2]), "=r"(Ahi[s][3]) : "r"(ah));
        }
    }

    float la0 = 0.0f, la1 = 0.0f;

    for (int c = 0; c < 8; c++) {
        asm volatile("cp.async.wait_group 0;");  // chunk c resident
        __syncthreads();                          // visible to all; buf (c+1)&1 free

        if (c + 1 < 8) {
            size_t gsrc = __cvta_generic_to_global(g_B[c + 1]);
            const uint32_t dst = sb + SM_B0 + ((c + 1) & 1) * CHUNK_B;
            #pragma unroll
            for (int i = 0; i < 9; i++) {
                int o = (i * 256 + tid) * 16;
                asm volatile("cp.async.cg.shared.global [%0], [%1], 16;"
                             :: "r"(dst + o), "l"(gsrc + o));
            }
            asm volatile("cp.async.commit_group;");
        }

        const uint32_t Bb = sb + SM_B0 + (c & 1) * CHUNK_B
                          + ((lane >> 4) * 8 + (lane & 7)) * ROWB + ((lane >> 3) & 1) * 16;

        #pragma unroll
        for (int half = 0; half < 2; half++) {
            const int cc = 2 * c + half;
            float acc[8][4];
            #pragma unroll
            for (int t = 0; t < 8; t++) { acc[t][0]=0.f; acc[t][1]=0.f; acc[t][2]=0.f; acc[t][3]=0.f; }

            #pragma unroll
            for (int t2 = 0; t2 < 4; t2++) {
                #pragma unroll
                for (int s = 0; s < 4; s++) {
                    uint32_t bh0, bh1, bh2, bh3, bl0, bl1, bl2, bl3;
                    const uint32_t ab = Bb + (half * 64 + t2 * 16) * ROWB + s * 32;
                    asm volatile("ldmatrix.sync.aligned.m8n8.x4.shared.b16 {%0,%1,%2,%3}, [%4];"
                                 : "=r"(bh0), "=r"(bh1), "=r"(bh2), "=r"(bh3) : "r"(ab));
                    asm volatile("ldmatrix.sync.aligned.m8n8.x4.shared.b16 {%0,%1,%2,%3}, [%4];"
                                 : "=r"(bl0), "=r"(bl1), "=r"(bl2), "=r"(bl3) : "r"(ab + HALF_BB));
                    HMMA(acc[2*t2],   Ahi[s], bh0, bh1);
                    HMMA(acc[2*t2+1], Ahi[s], bh2, bh3);
                    HMMA(acc[2*t2],   Ahi[s], bl0, bl1);
                    HMMA(acc[2*t2+1], Ahi[s], bl2, bl3);
                }
            }

            // epilogue for component cc: quad (wx . G) + linear (wxe . -2b)
            const float* bm = (const float*)(smem + SM_BM) + cc * 64;
            float p0 = 0.f, p1 = 0.f;
            #pragma unroll
            for (int i = 0; i < 16; i++) {
                const int j = (i >> 1) * 8 + 2 * (lane & 3) + (i & 1);
                const float b = bm[j];
                __nv_bfloat162 lp0 = *reinterpret_cast<__nv_bfloat162*>(&xlp[0][i >> 1]);
                __nv_bfloat162 lp1 = *reinterpret_cast<__nv_bfloat162*>(&xlp[1][i >> 1]);
                const float l0 = __bfloat162float((i & 1) ? lp0.y : lp0.x);
                const float l1 = __bfloat162float((i & 1) ? lp1.y : lp1.x);
                p0 = fmaf(wx[0][i] - l0, b, p0);
                p1 = fmaf(wx[1][i] - l1, b, p1);
            }
            #pragma unroll
            for (int t = 0; t < 8; t++) {
                p0 = fmaf(wx[0][t*2],   acc[t][0], p0);
                p0 = fmaf(wx[0][t*2+1], acc[t][1], p0);
                p1 = fmaf(wx[1][t*2],   acc[t][2], p1);
                p1 = fmaf(wx[1][t*2+1], acc[t][3], p1);
            }
            p0 += __shfl_xor_sync(0xFFFFFFFFu, p0, 1); p0 += __shfl_xor_sync(0xFFFFFFFFu, p0, 2);
            p1 += __shfl_xor_sync(0xFFFFFFFFu, p1, 1); p1 += __shfl_xor_sync(0xFFFFFFFFu, p1, 2);

            const float wc = *(float*)(smem + SM_WKC + 4 * cc);
            const float kc = *(float*)(smem + SM_WKC + 64 + 4 * cc);
            la0 = fmaf(wc, __logf(p0 + kc), la0);
            la1 = fmaf(wc, __logf(p1 + kc), la1);
        }
    }

    if ((lane & 3) == 0) {
        const int r0 = wid * 16 + (lane >> 2);
        out[base + r0]     = __expf(la0);
        out[base + r0 + 8] = __expf(la1);
    }
}

// ---------------- launch ----------------
extern "C" void kernel_launch(void* const* d_in, const int* in_sizes, int n_in,
                              void* d_out, int out_size)
{
    const float* X     = (const float*)d_in[0];   // [N, 64]
    const float* Ainv  = (const float*)d_in[1];   // [16, 64, 64]
    const float* Means = (const float*)d_in[2];   // [16, 64]
    const float* W     = (const float*)d_in[3];   // [16]
    float* out = (float*)d_out;

    const int N = in_sizes[0] / 64;

    cudaFuncSetAttribute(gmm_hmma_kernel, cudaFuncAttributeMaxDynamicSharedMemorySize, SMEM_BYTES);

    precomp1<<<132, 256>>>(Ainv, Means);
    precomp2<<<1, 32>>>(Means);
    gmm_hmma_kernel<<<N / 128, 256, SMEM_BYTES>>>(X, W, out, N);
}